// round 1
// baseline (speedup 1.0000x reference)
#include <cuda_runtime.h>

// Problem constants (fixed shapes for this problem)
#define NN 10000
#define DD 128
#define MAXE 512          // max nonzeros per row (binomial(10000,0.003) max ~55; huge margin)
#define SCAN_THREADS 128

// Scratch: per-node score = inputs @ H_v  (allocation-free per harness rules)
__device__ float g_score[NN];

// ---------------------------------------------------------------------------
// Kernel 1: score[j] = dot(inputs[j,:], H_v)   — one warp per row
// D=128 -> exactly 32 float4 per row, one per lane.
// ---------------------------------------------------------------------------
__global__ __launch_bounds__(128) void score_kernel(
    const float* __restrict__ inputs, const float* __restrict__ Hv)
{
    int row  = blockIdx.x * (blockDim.x >> 5) + (threadIdx.x >> 5);
    int lane = threadIdx.x & 31;
    if (row >= NN) return;
    const float4* ip = reinterpret_cast<const float4*>(inputs + (size_t)row * DD);
    const float4* hv = reinterpret_cast<const float4*>(Hv);
    float4 a = ip[lane];
    float4 h = hv[lane];
    float acc = a.x * h.x + a.y * h.y + a.z * h.z + a.w * h.w;
    #pragma unroll
    for (int off = 16; off > 0; off >>= 1)
        acc += __shfl_xor_sync(0xffffffffu, acc, off);
    if (lane == 0) g_score[row] = acc;
}

// ---------------------------------------------------------------------------
// Kernel 2: one CTA (128 threads) per row.
//   Pass 1: scan adj row (float4), compact nonzeros -> shared (idx, val)
//   Pass 2: softmax over ~31 compacted logits
//   Pass 3: out[row, d] = sum_k w_k * inputs[j_k, d]   (thread d = tid)
// ---------------------------------------------------------------------------
__global__ __launch_bounds__(SCAN_THREADS) void attn_kernel(
    const float* __restrict__ inputs,
    const float* __restrict__ adj,
    float* __restrict__ out)
{
    __shared__ int   s_idx[MAXE];
    __shared__ float s_w[MAXE];
    __shared__ int   s_cnt;
    __shared__ float s_red[4];

    const int row = blockIdx.x;
    const int tid = threadIdx.x;

    if (tid == 0) s_cnt = 0;
    __syncthreads();

    // ---- Pass 1: scan + compact -------------------------------------------
    const float4* arow = reinterpret_cast<const float4*>(adj + (size_t)row * NN);
    for (int v = tid; v < NN / 4; v += SCAN_THREADS) {
        float4 a = __ldg(&arow[v]);
        int j = v << 2;
        if (a.x != 0.0f) { int p = atomicAdd(&s_cnt, 1); s_idx[p] = j;     s_w[p] = a.x; }
        if (a.y != 0.0f) { int p = atomicAdd(&s_cnt, 1); s_idx[p] = j + 1; s_w[p] = a.y; }
        if (a.z != 0.0f) { int p = atomicAdd(&s_cnt, 1); s_idx[p] = j + 2; s_w[p] = a.z; }
        if (a.w != 0.0f) { int p = atomicAdd(&s_cnt, 1); s_idx[p] = j + 3; s_w[p] = a.w; }
    }
    __syncthreads();
    const int cnt = s_cnt;

    // ---- Pass 2: logits + softmax over the compacted list ------------------
    // logit_k = a_k * score[j_k]
    for (int k = tid; k < cnt; k += SCAN_THREADS)
        s_w[k] = s_w[k] * g_score[s_idx[k]];
    __syncthreads();

    // block max
    float m = -1e30f;
    for (int k = tid; k < cnt; k += SCAN_THREADS) m = fmaxf(m, s_w[k]);
    #pragma unroll
    for (int off = 16; off > 0; off >>= 1)
        m = fmaxf(m, __shfl_xor_sync(0xffffffffu, m, off));
    if ((tid & 31) == 0) s_red[tid >> 5] = m;
    __syncthreads();
    m = fmaxf(fmaxf(s_red[0], s_red[1]), fmaxf(s_red[2], s_red[3]));
    __syncthreads();

    // exp + block sum
    float s = 0.0f;
    for (int k = tid; k < cnt; k += SCAN_THREADS) {
        float e = __expf(s_w[k] - m);
        s_w[k] = e;
        s += e;
    }
    #pragma unroll
    for (int off = 16; off > 0; off >>= 1)
        s += __shfl_xor_sync(0xffffffffu, s, off);
    if ((tid & 31) == 0) s_red[tid >> 5] = s;
    __syncthreads();          // also makes s_w (exp'd) visible to all threads
    s = s_red[0] + s_red[1] + s_red[2] + s_red[3];
    const float inv = 1.0f / s;

    // ---- Pass 3: weighted aggregation (thread d = tid, d in [0,128)) -------
    float acc = 0.0f;
    int k = 0;
    // unroll-by-4 for memory-level parallelism (gathers are L2-resident)
    for (; k + 4 <= cnt; k += 4) {
        float w0 = s_w[k],     w1 = s_w[k + 1], w2 = s_w[k + 2], w3 = s_w[k + 3];
        const float* r0 = inputs + (size_t)s_idx[k]     * DD;
        const float* r1 = inputs + (size_t)s_idx[k + 1] * DD;
        const float* r2 = inputs + (size_t)s_idx[k + 2] * DD;
        const float* r3 = inputs + (size_t)s_idx[k + 3] * DD;
        acc += w0 * __ldg(&r0[tid]);
        acc += w1 * __ldg(&r1[tid]);
        acc += w2 * __ldg(&r2[tid]);
        acc += w3 * __ldg(&r3[tid]);
    }
    for (; k < cnt; k++)
        acc += s_w[k] * __ldg(&inputs[(size_t)s_idx[k] * DD + tid]);

    out[(size_t)row * DD + tid] = acc * inv;
}

// ---------------------------------------------------------------------------
extern "C" void kernel_launch(void* const* d_in, const int* in_sizes, int n_in,
                              void* d_out, int out_size)
{
    const float* inputs = (const float*)d_in[0];  // [10000,128]
    const float* adj    = (const float*)d_in[1];  // [10000,10000]
    const float* Hv     = (const float*)d_in[2];  // [128,1]
    float* out          = (float*)d_out;          // [10000,128]

    // score_kernel: 4 warps/CTA -> 2500 CTAs cover 10000 rows
    score_kernel<<<(NN + 3) / 4, 128>>>(inputs, Hv);
    // attn_kernel: one CTA per row
    attn_kernel<<<NN, SCAN_THREADS>>>(inputs, adj, out);
}

// round 2
// speedup vs baseline: 1.1790x; 1.1790x over previous
#include <cuda_runtime.h>

#define NN 10000
#define DD 128
#define MAXE 512
#define SCAN_THREADS 128
#define NV4 (NN / 4)          // 2500 float4 per adj row

__device__ float g_score[NN];

// ---------------------------------------------------------------------------
// Kernel 1: score[j] = dot(inputs[j,:], H_v)   — one warp per row
// ---------------------------------------------------------------------------
__global__ __launch_bounds__(128) void score_kernel(
    const float* __restrict__ inputs, const float* __restrict__ Hv)
{
    int row  = blockIdx.x * (blockDim.x >> 5) + (threadIdx.x >> 5);
    int lane = threadIdx.x & 31;
    if (row >= NN) return;
    const float4* ip = reinterpret_cast<const float4*>(inputs + (size_t)row * DD);
    const float4* hv = reinterpret_cast<const float4*>(Hv);
    float4 a = ip[lane];
    float4 h = hv[lane];
    float acc = a.x * h.x + a.y * h.y + a.z * h.z + a.w * h.w;
    #pragma unroll
    for (int off = 16; off > 0; off >>= 1)
        acc += __shfl_xor_sync(0xffffffffu, acc, off);
    if (lane == 0) g_score[row] = acc;
}

// ---------------------------------------------------------------------------
// Kernel 2: one CTA (128 threads) per row.
// ---------------------------------------------------------------------------
__global__ __launch_bounds__(SCAN_THREADS) void attn_kernel(
    const float* __restrict__ inputs,
    const float* __restrict__ adj,
    float* __restrict__ out)
{
    __shared__ int   s_idx[MAXE];
    __shared__ float s_w[MAXE];
    __shared__ int   s_cnt;
    __shared__ float s_red[4];

    const int row = blockIdx.x;
    const int tid = threadIdx.x;

    if (tid == 0) s_cnt = 0;
    __syncthreads();

    const float4* arow = reinterpret_cast<const float4*>(adj + (size_t)row * NN);

    // Compaction: insert nonzeros with the logit fused in (a * score[j]).
    auto proc = [&](float4 a, int j) {
        if (a.x != 0.0f) { int p = atomicAdd(&s_cnt, 1); s_idx[p] = j;     s_w[p] = a.x * g_score[j];     }
        if (a.y != 0.0f) { int p = atomicAdd(&s_cnt, 1); s_idx[p] = j + 1; s_w[p] = a.y * g_score[j + 1]; }
        if (a.z != 0.0f) { int p = atomicAdd(&s_cnt, 1); s_idx[p] = j + 2; s_w[p] = a.z * g_score[j + 2]; }
        if (a.w != 0.0f) { int p = atomicAdd(&s_cnt, 1); s_idx[p] = j + 3; s_w[p] = a.w * g_score[j + 3]; }
    };

    // ---- Pass 1: scan with front-batched loads (MLP=4), streaming hint -----
    // Main region: v in [0, 2048) — 4 iterations, no predicates needed.
    #pragma unroll
    for (int i = 0; i < 4; i++) {
        int v0 = tid + i * 512;
        // 4 independent loads issued back-to-back before any compaction logic
        float4 a0 = __ldcs(&arow[v0]);
        float4 a1 = __ldcs(&arow[v0 + 128]);
        float4 a2 = __ldcs(&arow[v0 + 256]);
        float4 a3 = __ldcs(&arow[v0 + 384]);
        proc(a0, v0 << 2);
        proc(a1, (v0 + 128) << 2);
        proc(a2, (v0 + 256) << 2);
        proc(a3, (v0 + 384) << 2);
    }
    // Tail region: v in [2048, 2500)
    {
        int v0 = 2048 + tid;            // < 2500 always
        int v1 = v0 + 128;              // < 2500 always (2303 max)
        int v2 = v0 + 256;              // < 2500 always (2431 max)
        int v3 = v0 + 384;              // needs tid < 68
        float4 a0 = __ldcs(&arow[v0]);
        float4 a1 = __ldcs(&arow[v1]);
        float4 a2 = __ldcs(&arow[v2]);
        float4 a3 = make_float4(0.f, 0.f, 0.f, 0.f);
        if (v3 < NV4) a3 = __ldcs(&arow[v3]);
        proc(a0, v0 << 2);
        proc(a1, v1 << 2);
        proc(a2, v2 << 2);
        if (v3 < NV4) proc(a3, v3 << 2);
    }
    __syncthreads();
    const int cnt = s_cnt;

    // ---- Pass 2: softmax over the compacted logits --------------------------
    float m = -1e30f;
    for (int k = tid; k < cnt; k += SCAN_THREADS) m = fmaxf(m, s_w[k]);
    #pragma unroll
    for (int off = 16; off > 0; off >>= 1)
        m = fmaxf(m, __shfl_xor_sync(0xffffffffu, m, off));
    if ((tid & 31) == 0) s_red[tid >> 5] = m;
    __syncthreads();
    m = fmaxf(fmaxf(s_red[0], s_red[1]), fmaxf(s_red[2], s_red[3]));
    __syncthreads();

    float s = 0.0f;
    for (int k = tid; k < cnt; k += SCAN_THREADS) {
        float e = __expf(s_w[k] - m);
        s_w[k] = e;
        s += e;
    }
    #pragma unroll
    for (int off = 16; off > 0; off >>= 1)
        s += __shfl_xor_sync(0xffffffffu, s, off);
    if ((tid & 31) == 0) s_red[tid >> 5] = s;
    __syncthreads();
    s = s_red[0] + s_red[1] + s_red[2] + s_red[3];
    const float inv = 1.0f / s;

    // ---- Pass 3: weighted aggregation (thread d = tid) ----------------------
    float acc = 0.0f;
    int k = 0;
    for (; k + 4 <= cnt; k += 4) {
        float w0 = s_w[k],     w1 = s_w[k + 1], w2 = s_w[k + 2], w3 = s_w[k + 3];
        const float* r0 = inputs + (size_t)s_idx[k]     * DD;
        const float* r1 = inputs + (size_t)s_idx[k + 1] * DD;
        const float* r2 = inputs + (size_t)s_idx[k + 2] * DD;
        const float* r3 = inputs + (size_t)s_idx[k + 3] * DD;
        acc += w0 * __ldg(&r0[tid]);
        acc += w1 * __ldg(&r1[tid]);
        acc += w2 * __ldg(&r2[tid]);
        acc += w3 * __ldg(&r3[tid]);
    }
    for (; k < cnt; k++)
        acc += s_w[k] * __ldg(&inputs[(size_t)s_idx[k] * DD + tid]);

    out[(size_t)row * DD + tid] = acc * inv;
}

// ---------------------------------------------------------------------------
extern "C" void kernel_launch(void* const* d_in, const int* in_sizes, int n_in,
                              void* d_out, int out_size)
{
    const float* inputs = (const float*)d_in[0];  // [10000,128]
    const float* adj    = (const float*)d_in[1];  // [10000,10000]
    const float* Hv     = (const float*)d_in[2];  // [128,1]
    float* out          = (float*)d_out;          // [10000,128]

    score_kernel<<<(NN + 3) / 4, 128>>>(inputs, Hv);
    attn_kernel<<<NN, SCAN_THREADS>>>(inputs, adj, out);
}

// round 3
// speedup vs baseline: 1.2635x; 1.0717x over previous
#include <cuda_runtime.h>

#define NN 10000
#define DD 128
#define MAXE 512
#define SCAN_THREADS 128
#define NV4 (NN / 4)          // 2500 float4 per adj row

__device__ float g_score[NN];

// ---------------------------------------------------------------------------
// Kernel 1: score[j] = dot(inputs[j,:], H_v)   — one warp per row
// ---------------------------------------------------------------------------
__global__ __launch_bounds__(128) void score_kernel(
    const float* __restrict__ inputs, const float* __restrict__ Hv)
{
    int row  = blockIdx.x * (blockDim.x >> 5) + (threadIdx.x >> 5);
    int lane = threadIdx.x & 31;
    if (row >= NN) return;
    const float4* ip = reinterpret_cast<const float4*>(inputs + (size_t)row * DD);
    const float4* hv = reinterpret_cast<const float4*>(Hv);
    float4 a = ip[lane];
    float4 h = hv[lane];
    float acc = a.x * h.x + a.y * h.y + a.z * h.z + a.w * h.w;
    #pragma unroll
    for (int off = 16; off > 0; off >>= 1)
        acc += __shfl_xor_sync(0xffffffffu, acc, off);
    if (lane == 0) g_score[row] = acc;
}

// ---------------------------------------------------------------------------
// Kernel 2: one CTA (128 threads = 4 warps) per row.
// ---------------------------------------------------------------------------
__global__ __launch_bounds__(SCAN_THREADS) void attn_kernel(
    const float* __restrict__ inputs,
    const float* __restrict__ adj,
    float* __restrict__ out)
{
    __shared__ int   s_idx[MAXE];
    __shared__ float s_w[MAXE];
    __shared__ float s_part[4 * DD];   // 4 warp-partial output vectors
    __shared__ int   s_cnt;
    __shared__ float s_red[4];

    const int row  = blockIdx.x;
    const int tid  = threadIdx.x;
    const int wid  = tid >> 5;
    const int lane = tid & 31;

    if (tid == 0) s_cnt = 0;
    __syncthreads();

    const float4* arow = reinterpret_cast<const float4*>(adj + (size_t)row * NN);

    // Compaction: store raw (index, adj value). No global loads inside.
    auto proc = [&](float4 a, int j) {
        if (a.x != 0.0f) { int p = atomicAdd(&s_cnt, 1); s_idx[p] = j;     s_w[p] = a.x; }
        if (a.y != 0.0f) { int p = atomicAdd(&s_cnt, 1); s_idx[p] = j + 1; s_w[p] = a.y; }
        if (a.z != 0.0f) { int p = atomicAdd(&s_cnt, 1); s_idx[p] = j + 2; s_w[p] = a.z; }
        if (a.w != 0.0f) { int p = atomicAdd(&s_cnt, 1); s_idx[p] = j + 3; s_w[p] = a.w; }
    };

    // ---- Pass 1: scan with front-batched loads (MLP=4), streaming hint -----
    #pragma unroll
    for (int i = 0; i < 4; i++) {
        int v0 = tid + i * 512;
        float4 a0 = __ldcs(&arow[v0]);
        float4 a1 = __ldcs(&arow[v0 + 128]);
        float4 a2 = __ldcs(&arow[v0 + 256]);
        float4 a3 = __ldcs(&arow[v0 + 384]);
        proc(a0, v0 << 2);
        proc(a1, (v0 + 128) << 2);
        proc(a2, (v0 + 256) << 2);
        proc(a3, (v0 + 384) << 2);
    }
    {   // tail: v in [2048, 2500)
        int v0 = 2048 + tid;
        int v1 = v0 + 128;
        int v2 = v0 + 256;
        int v3 = v0 + 384;                 // valid only for tid < 68
        float4 a0 = __ldcs(&arow[v0]);
        float4 a1 = __ldcs(&arow[v1]);
        float4 a2 = __ldcs(&arow[v2]);
        float4 a3 = make_float4(0.f, 0.f, 0.f, 0.f);
        if (v3 < NV4) a3 = __ldcs(&arow[v3]);
        proc(a0, v0 << 2);
        proc(a1, v1 << 2);
        proc(a2, v2 << 2);
        if (v3 < NV4) proc(a3, v3 << 2);
    }
    __syncthreads();
    const int cnt = s_cnt;

    // ---- Pass 2a: logits (parallel gather of scores, one exposed latency) --
    for (int k = tid; k < cnt; k += SCAN_THREADS)
        s_w[k] = s_w[k] * __ldg(&g_score[s_idx[k]]);
    __syncthreads();

    // ---- Pass 2b: softmax over compacted logits ----------------------------
    float m = -1e30f;
    for (int k = tid; k < cnt; k += SCAN_THREADS) m = fmaxf(m, s_w[k]);
    #pragma unroll
    for (int off = 16; off > 0; off >>= 1)
        m = fmaxf(m, __shfl_xor_sync(0xffffffffu, m, off));
    if (lane == 0) s_red[wid] = m;
    __syncthreads();
    m = fmaxf(fmaxf(s_red[0], s_red[1]), fmaxf(s_red[2], s_red[3]));
    __syncthreads();

    float s = 0.0f;
    for (int k = tid; k < cnt; k += SCAN_THREADS) {
        float e = __expf(s_w[k] - m);
        s_w[k] = e;
        s += e;
    }
    #pragma unroll
    for (int off = 16; off > 0; off >>= 1)
        s += __shfl_xor_sync(0xffffffffu, s, off);
    if (lane == 0) s_red[wid] = s;
    __syncthreads();
    s = s_red[0] + s_red[1] + s_red[2] + s_red[3];
    const float inv = 1.0f / s;

    // ---- Pass 3: warp-split float4 gather ----------------------------------
    // Warp w handles neighbors k = w, w+4, w+8, ... Each lane loads float4:
    // warp covers all 128 features of a neighbor row per step.
    const float4* inp4 = reinterpret_cast<const float4*>(inputs);
    float4 acc = make_float4(0.f, 0.f, 0.f, 0.f);
    int k = wid;
    // 4 neighbors in flight per warp
    for (; k + 12 < cnt; k += 16) {
        float w0 = s_w[k],      w1 = s_w[k + 4],  w2 = s_w[k + 8],  w3 = s_w[k + 12];
        int   j0 = s_idx[k],    j1 = s_idx[k + 4], j2 = s_idx[k + 8], j3 = s_idx[k + 12];
        float4 x0 = __ldg(&inp4[(size_t)j0 * 32 + lane]);
        float4 x1 = __ldg(&inp4[(size_t)j1 * 32 + lane]);
        float4 x2 = __ldg(&inp4[(size_t)j2 * 32 + lane]);
        float4 x3 = __ldg(&inp4[(size_t)j3 * 32 + lane]);
        acc.x += w0 * x0.x + w1 * x1.x + w2 * x2.x + w3 * x3.x;
        acc.y += w0 * x0.y + w1 * x1.y + w2 * x2.y + w3 * x3.y;
        acc.z += w0 * x0.z + w1 * x1.z + w2 * x2.z + w3 * x3.z;
        acc.w += w0 * x0.w + w1 * x1.w + w2 * x2.w + w3 * x3.w;
    }
    for (; k < cnt; k += 4) {
        float w0 = s_w[k];
        int   j0 = s_idx[k];
        float4 x0 = __ldg(&inp4[(size_t)j0 * 32 + lane]);
        acc.x += w0 * x0.x; acc.y += w0 * x0.y;
        acc.z += w0 * x0.z; acc.w += w0 * x0.w;
    }
    // store warp partials: s_part[wid*128 + lane*4 + c] = feature (lane*4+c)
    reinterpret_cast<float4*>(s_part)[wid * 32 + lane] = acc;
    __syncthreads();

    float v = (s_part[tid] + s_part[DD + tid] + s_part[2 * DD + tid] + s_part[3 * DD + tid]) * inv;
    out[(size_t)row * DD + tid] = v;
}

// ---------------------------------------------------------------------------
extern "C" void kernel_launch(void* const* d_in, const int* in_sizes, int n_in,
                              void* d_out, int out_size)
{
    const float* inputs = (const float*)d_in[0];  // [10000,128]
    const float* adj    = (const float*)d_in[1];  // [10000,10000]
    const float* Hv     = (const float*)d_in[2];  // [128,1]
    float* out          = (float*)d_out;          // [10000,128]

    score_kernel<<<(NN + 3) / 4, 128>>>(inputs, Hv);
    attn_kernel<<<NN, SCAN_THREADS>>>(inputs, adj, out);
}

// round 5
// speedup vs baseline: 1.2724x; 1.0070x over previous
#include <cuda_runtime.h>

#define NN 10000
#define DD 128
#define MAXE 160            // max nonzeros/row: mean ~31, extreme tail ~70; 160 is safe
#define GRID 1184           // persistent grid: ~8 CTAs per SM
#define NV4 (NN / 4)        // 2500 float4 per adj row

__device__ float g_score[NN];

#define EPI_BAR() asm volatile("bar.sync 1, 128;" ::: "memory")

// ---------------------------------------------------------------------------
// Kernel 1: score[j] = dot(inputs[j,:], H_v)   — one warp per row
// ---------------------------------------------------------------------------
__global__ __launch_bounds__(128) void score_kernel(
    const float* __restrict__ inputs, const float* __restrict__ Hv)
{
    int row  = blockIdx.x * (blockDim.x >> 5) + (threadIdx.x >> 5);
    int lane = threadIdx.x & 31;
    if (row >= NN) return;
    const float4* ip = reinterpret_cast<const float4*>(inputs + (size_t)row * DD);
    const float4* hv = reinterpret_cast<const float4*>(Hv);
    float4 a = ip[lane];
    float4 h = hv[lane];
    float acc = a.x * h.x + a.y * h.y + a.z * h.z + a.w * h.w;
    #pragma unroll
    for (int off = 16; off > 0; off >>= 1)
        acc += __shfl_xor_sync(0xffffffffu, acc, off);
    if (lane == 0) g_score[row] = acc;
}

// ---------------------------------------------------------------------------
// Kernel 2: persistent CTAs, 256 threads.
//   warps 0-3: scan/compact row i into buf[i&1]
//   warps 4-7: softmax + gather + store for row i-1 from buf[(i-1)&1]
// ---------------------------------------------------------------------------
__global__ __launch_bounds__(256, 8) void attn_kernel(
    const float* __restrict__ inputs,
    const float* __restrict__ adj,
    float* __restrict__ out)
{
    // NOTE: every array accessed via float4 casts must be 16B-aligned
    // (R4 failure: s_part landed at offset 2568 -> misaligned STS.128 trap).
    __shared__ alignas(16) float s_w[2][MAXE];
    __shared__ alignas(16) float s_part[4 * DD];
    __shared__ alignas(16) int   s_idx[2][MAXE];
    __shared__ int   s_cnt[2];
    __shared__ float s_red[4];

    const int tid     = threadIdx.x;
    const bool isScan = tid < 128;
    const int ltid    = tid & 127;
    const int lane    = tid & 31;
    const int ewid    = ltid >> 5;      // warp index within group

    if (tid < 2) s_cnt[tid] = 0;
    __syncthreads();

    const int bid   = blockIdx.x;
    const int nrows = (NN - bid + GRID - 1) / GRID;   // rows: bid + i*GRID

    for (int it = 0; it <= nrows; it++) {
        if (isScan) {
            if (it < nrows) {
                // ---------------- SCAN row -> buffer b ----------------
                const int   row = bid + it * GRID;
                const int   b   = it & 1;
                int*   bidx = s_idx[b];
                float* bw   = s_w[b];
                const float4* arow = reinterpret_cast<const float4*>(adj + (size_t)row * NN);

                auto proc = [&](float4 a, int j) {
                    if (a.x != 0.0f) { int p = atomicAdd(&s_cnt[b], 1); bidx[p] = j;     bw[p] = a.x; }
                    if (a.y != 0.0f) { int p = atomicAdd(&s_cnt[b], 1); bidx[p] = j + 1; bw[p] = a.y; }
                    if (a.z != 0.0f) { int p = atomicAdd(&s_cnt[b], 1); bidx[p] = j + 2; bw[p] = a.z; }
                    if (a.w != 0.0f) { int p = atomicAdd(&s_cnt[b], 1); bidx[p] = j + 3; bw[p] = a.w; }
                };

                #pragma unroll
                for (int i = 0; i < 4; i++) {
                    int v0 = ltid + i * 512;
                    float4 a0 = __ldcs(&arow[v0]);
                    float4 a1 = __ldcs(&arow[v0 + 128]);
                    float4 a2 = __ldcs(&arow[v0 + 256]);
                    float4 a3 = __ldcs(&arow[v0 + 384]);
                    proc(a0, v0 << 2);
                    proc(a1, (v0 + 128) << 2);
                    proc(a2, (v0 + 256) << 2);
                    proc(a3, (v0 + 384) << 2);
                }
                {   // tail: v in [2048, 2500)
                    int v0 = 2048 + ltid;
                    int v1 = v0 + 128;
                    int v2 = v0 + 256;
                    int v3 = v0 + 384;              // valid only for ltid < 68
                    float4 a0 = __ldcs(&arow[v0]);
                    float4 a1 = __ldcs(&arow[v1]);
                    float4 a2 = __ldcs(&arow[v2]);
                    float4 a3 = make_float4(0.f, 0.f, 0.f, 0.f);
                    if (v3 < NV4) a3 = __ldcs(&arow[v3]);
                    proc(a0, v0 << 2);
                    proc(a1, v1 << 2);
                    proc(a2, v2 << 2);
                    if (v3 < NV4) proc(a3, v3 << 2);
                }
            }
        } else {
            if (it >= 1) {
                // ---------------- EPILOGUE row i-1 from buffer b ----------------
                const int   row = bid + (it - 1) * GRID;
                const int   b   = (it - 1) & 1;
                int*   bidx = s_idx[b];
                float* bw   = s_w[b];
                const int cnt = s_cnt[b];

                // logits: parallel score gather
                for (int k = ltid; k < cnt; k += 128)
                    bw[k] = bw[k] * __ldg(&g_score[bidx[k]]);
                EPI_BAR();

                // block max over 128 epi threads
                float m = -1e30f;
                for (int k = ltid; k < cnt; k += 128) m = fmaxf(m, bw[k]);
                #pragma unroll
                for (int off = 16; off > 0; off >>= 1)
                    m = fmaxf(m, __shfl_xor_sync(0xffffffffu, m, off));
                if (lane == 0) s_red[ewid] = m;
                EPI_BAR();
                m = fmaxf(fmaxf(s_red[0], s_red[1]), fmaxf(s_red[2], s_red[3]));
                EPI_BAR();

                float s = 0.0f;
                for (int k = ltid; k < cnt; k += 128) {
                    float e = __expf(bw[k] - m);
                    bw[k] = e;
                    s += e;
                }
                #pragma unroll
                for (int off = 16; off > 0; off >>= 1)
                    s += __shfl_xor_sync(0xffffffffu, s, off);
                if (lane == 0) s_red[ewid] = s;
                EPI_BAR();
                s = s_red[0] + s_red[1] + s_red[2] + s_red[3];
                const float inv = 1.0f / s;

                // warp-split float4 gather: warp w -> neighbors k = w, w+4, ...
                const float4* inp4 = reinterpret_cast<const float4*>(inputs);
                float4 acc = make_float4(0.f, 0.f, 0.f, 0.f);
                int k = ewid;
                for (; k + 12 < cnt; k += 16) {
                    float w0 = bw[k],      w1 = bw[k + 4],  w2 = bw[k + 8],  w3 = bw[k + 12];
                    int   j0 = bidx[k],    j1 = bidx[k + 4], j2 = bidx[k + 8], j3 = bidx[k + 12];
                    float4 x0 = __ldg(&inp4[(size_t)j0 * 32 + lane]);
                    float4 x1 = __ldg(&inp4[(size_t)j1 * 32 + lane]);
                    float4 x2 = __ldg(&inp4[(size_t)j2 * 32 + lane]);
                    float4 x3 = __ldg(&inp4[(size_t)j3 * 32 + lane]);
                    acc.x += w0 * x0.x + w1 * x1.x + w2 * x2.x + w3 * x3.x;
                    acc.y += w0 * x0.y + w1 * x1.y + w2 * x2.y + w3 * x3.y;
                    acc.z += w0 * x0.z + w1 * x1.z + w2 * x2.z + w3 * x3.z;
                    acc.w += w0 * x0.w + w1 * x1.w + w2 * x2.w + w3 * x3.w;
                }
                for (; k < cnt; k += 4) {
                    float w0 = bw[k];
                    int   j0 = bidx[k];
                    float4 x0 = __ldg(&inp4[(size_t)j0 * 32 + lane]);
                    acc.x += w0 * x0.x; acc.y += w0 * x0.y;
                    acc.z += w0 * x0.z; acc.w += w0 * x0.w;
                }
                reinterpret_cast<float4*>(s_part)[ewid * 32 + lane] = acc;
                EPI_BAR();

                float v = (s_part[ltid] + s_part[DD + ltid] +
                           s_part[2 * DD + ltid] + s_part[3 * DD + ltid]) * inv;
                out[(size_t)row * DD + ltid] = v;

                // release buffer for the scan group's it+1 use
                if (ltid == 0) s_cnt[b] = 0;
            }
        }
        __syncthreads();   // handoff: buffer b full / buffer b^1 free
    }
}

// ---------------------------------------------------------------------------
extern "C" void kernel_launch(void* const* d_in, const int* in_sizes, int n_in,
                              void* d_out, int out_size)
{
    const float* inputs = (const float*)d_in[0];  // [10000,128]
    const float* adj    = (const float*)d_in[1];  // [10000,10000]
    const float* Hv     = (const float*)d_in[2];  // [128,1]
    float* out          = (float*)d_out;          // [10000,128]

    score_kernel<<<(NN + 3) / 4, 128>>>(inputs, Hv);
    attn_kernel<<<GRID, 256>>>(inputs, adj, out);
}